// round 4
// baseline (speedup 1.0000x reference)
#include <cuda_runtime.h>
#include <math.h>

// Problem constants
#define NTOK 1024      // B*S
#define DMODEL 1024
#define NH 16
#define HDIM 64
#define SEQ 256
#define NB 4
#define NE 8
#define DHID 2048
#define MAXM 1024      // max rows per expert (each token contributes <=1 slot per expert)

// ---------------- scratch (device globals; no allocation allowed) ----------------
__device__ float g_feat[NTOK * DMODEL];
__device__ float g_xn[NTOK * DMODEL];
__device__ float g_q[NTOK * DMODEL];
__device__ float g_k[NTOK * DMODEL];
__device__ float g_v[NTOK * DMODEL];
__device__ float g_o[NTOK * DMODEL];
__device__ float g_h[NE * MAXM * DHID];    // 64 MB expert hidden
__device__ float g_y2[NE * MAXM * DMODEL]; // 32 MB expert output
__device__ int   g_cnt[NE];
__device__ int   g_ptok[NE * MAXM];
__device__ int   g_pos[NTOK * 2];
__device__ float g_wgt[NTOK * 2];

// ---------------- embedding ----------------
__global__ void embed_kernel(const int* __restrict__ et, const int* __restrict__ xi,
                             const float* __restrict__ ent, const float* __restrict__ maskemb,
                             const float* __restrict__ rel, const float* __restrict__ type)
{
    int tok = blockIdx.x, t = threadIdx.x;   // 256 threads, 1 float4 each
    int ty = et[tok];
    int xv = xi[tok];
    const float* src;
    if (ty == 0)      src = ent + (size_t)(((unsigned)xv) % 40000u) * DMODEL;
    else if (ty == 1) src = maskemb;
    else              src = rel + (size_t)(((unsigned)xv) % 1000u) * DMODEL;
    float4 s4 = ((const float4*)src)[t];
    float4 t4 = ((const float4*)(type + (size_t)ty * DMODEL))[t];
    float4 r = make_float4(s4.x + t4.x, s4.y + t4.y, s4.z + t4.z, s4.w + t4.w);
    ((float4*)(g_feat + (size_t)tok * DMODEL))[t] = r;
}

// ---------------- layernorm (block per row, 256 threads = 256 float4) ----------------
__global__ void ln_kernel(const float* __restrict__ x, const float* __restrict__ g,
                          const float* __restrict__ b, float* __restrict__ y)
{
    __shared__ float red[256];
    int row = blockIdx.x, t = threadIdx.x;
    float4 xv = ((const float4*)(x + (size_t)row * DMODEL))[t];
    red[t] = xv.x + xv.y + xv.z + xv.w;
    __syncthreads();
    #pragma unroll
    for (int off = 128; off > 0; off >>= 1) { if (t < off) red[t] += red[t + off]; __syncthreads(); }
    float m = red[0] * (1.0f / DMODEL);
    __syncthreads();
    float dx = xv.x - m, dy = xv.y - m, dz = xv.z - m, dw = xv.w - m;
    red[t] = dx * dx + dy * dy + dz * dz + dw * dw;
    __syncthreads();
    #pragma unroll
    for (int off = 128; off > 0; off >>= 1) { if (t < off) red[t] += red[t + off]; __syncthreads(); }
    float rs = rsqrtf(red[0] * (1.0f / DMODEL) + 1e-5f);
    float4 gv = ((const float4*)g)[t];
    float4 bv = ((const float4*)b)[t];
    float4 o = make_float4(dx * rs * gv.x + bv.x, dy * rs * gv.y + bv.y,
                           dz * rs * gv.z + bv.z, dw * rs * gv.w + bv.w);
    ((float4*)(y + (size_t)row * DMODEL))[t] = o;
}

// ---------------- SGEMM: C[M,N] (+)= op(A[M,K] @ W[K,N] + bias[N]) ----------------
// 64x64 tile, BK=16, 256 threads, 4x4 micro-tile.
// EXPERT: blockIdx.z selects expert; M comes from cnt[e]; W/bias/C offset per expert.
// GATHER: A rows indirect through gather[e*MAXM + m].
template<bool RELU, bool ACCUM, bool EXPERT, bool GATHER>
__global__ void __launch_bounds__(256)
sgemm(const float* __restrict__ A, const float* __restrict__ W,
      const float* __restrict__ bias, float* __restrict__ C,
      int M, int N, int K,
      const int* __restrict__ gather, const int* __restrict__ cnt,
      size_t aExpStride, size_t cExpStride)
{
    int e = EXPERT ? blockIdx.z : 0;
    int Mloc = EXPERT ? cnt[e] : M;
    int mBase = blockIdx.y * 64;
    if (mBase >= Mloc) return;
    int nBase = blockIdx.x * 64;

    const float* Ap = A + ((EXPERT && !GATHER) ? (size_t)e * aExpStride : 0);
    const float* Wp = W + (EXPERT ? (size_t)e * (size_t)K * N : 0);
    const float* bp = bias + (EXPERT ? (size_t)e * N : 0);
    float* Cp = C + (EXPERT ? (size_t)e * cExpStride : 0);
    const int* gp = GATHER ? (gather + e * MAXM) : (const int*)0;

    __shared__ __align__(16) float As[16][64];
    __shared__ __align__(16) float Bs[16][64];

    int tid = threadIdx.x;
    int tx = tid & 15, ty = tid >> 4;

    // A tile load mapping: 64 rows x 16 k, one float4 along k per thread
    int aRowT = tid >> 2;           // 0..63
    int aK4   = (tid & 3) << 2;     // 0,4,8,12
    int mrow  = mBase + aRowT;
    int mcl   = mrow < Mloc ? mrow : (Mloc - 1);
    int arow  = GATHER ? gp[mcl] : mcl;
    const float* aPtr = Ap + (size_t)arow * K + aK4;

    // B tile load mapping: 16 k-rows x 64 n, one float4 per thread
    int bRowT = tid >> 4;           // 0..15
    int bN4   = (tid & 15) << 2;    // 0..60
    const float* wPtr = Wp + (size_t)bRowT * N + nBase + bN4;

    float acc[4][4] = {};

    for (int k0 = 0; k0 < K; k0 += 16) {
        float4 av = *(const float4*)(aPtr + k0);
        As[aK4 + 0][aRowT] = av.x;
        As[aK4 + 1][aRowT] = av.y;
        As[aK4 + 2][aRowT] = av.z;
        As[aK4 + 3][aRowT] = av.w;
        *(float4*)&Bs[bRowT][bN4] = *(const float4*)(wPtr + (size_t)k0 * N);
        __syncthreads();
        #pragma unroll
        for (int kk = 0; kk < 16; kk++) {
            float4 a4 = *(const float4*)(&As[kk][ty << 2]);
            float4 b4 = *(const float4*)(&Bs[kk][tx << 2]);
            float ar[4] = {a4.x, a4.y, a4.z, a4.w};
            float br[4] = {b4.x, b4.y, b4.z, b4.w};
            #pragma unroll
            for (int i = 0; i < 4; i++)
                #pragma unroll
                for (int j = 0; j < 4; j++)
                    acc[i][j] = fmaf(ar[i], br[j], acc[i][j]);
        }
        __syncthreads();
    }

    #pragma unroll
    for (int i = 0; i < 4; i++) {
        int r = mBase + (ty << 2) + i;
        if (r < Mloc) {
            float* crow = Cp + (size_t)r * N + nBase + (tx << 2);
            #pragma unroll
            for (int j = 0; j < 4; j++) {
                float vv = acc[i][j] + bp[nBase + (tx << 2) + j];
                if (RELU) vv = fmaxf(vv, 0.0f);
                if (ACCUM) crow[j] += vv;
                else       crow[j] = vv;
            }
        }
    }
}

// ---------------- attention: block per (b,h,i); 256 threads ----------------
__global__ void __launch_bounds__(256)
attn_kernel(const float* __restrict__ q, const float* __restrict__ k,
            const float* __restrict__ v, const int* __restrict__ abt,
            const float* __restrict__ bias_emb, float* __restrict__ o)
{
    __shared__ float qs[HDIM];
    __shared__ float sc[SEQ];
    __shared__ float red[256];
    int bid = blockIdx.x;
    int i = bid & 255;
    int h = (bid >> 8) & 15;
    int b = bid >> 12;
    int t = threadIdx.x;

    int rowq = (b * SEQ + i) * DMODEL + h * HDIM;
    if (t < HDIM) qs[t] = q[rowq + t];
    __syncthreads();

    // scores: thread t handles key j = t
    int j = t;
    const float4* kr = (const float4*)(k + (size_t)(b * SEQ + j) * DMODEL + h * HDIM);
    float dot = 0.0f;
    #pragma unroll
    for (int d4 = 0; d4 < 16; d4++) {
        float4 kv = kr[d4];
        dot += qs[d4 * 4 + 0] * kv.x + qs[d4 * 4 + 1] * kv.y
             + qs[d4 * 4 + 2] * kv.z + qs[d4 * 4 + 3] * kv.w;
    }
    float bi = bias_emb[abt[(size_t)(b * SEQ + i) * SEQ + j] * NH + h];
    float s = dot * 0.125f + bi;   // DK^-0.5 = 1/8

    // softmax over j
    red[t] = s; __syncthreads();
    #pragma unroll
    for (int off = 128; off > 0; off >>= 1) { if (t < off) red[t] = fmaxf(red[t], red[t + off]); __syncthreads(); }
    float mx = red[0];
    __syncthreads();
    float p = expf(s - mx);
    red[t] = p; sc[t] = p;
    __syncthreads();
    #pragma unroll
    for (int off = 128; off > 0; off >>= 1) { if (t < off) red[t] += red[t + off]; __syncthreads(); }
    float inv = 1.0f / red[0];

    // output: d = t&63, group g = t>>6 covers 64 keys each
    int d = t & 63, grp = t >> 6;
    const float* vbase = v + (size_t)b * SEQ * DMODEL + h * HDIM + d;
    float a0 = 0, a1 = 0, a2 = 0, a3 = 0;
    int j0 = grp * 64;
    #pragma unroll 4
    for (int jj = 0; jj < 64; jj += 4) {
        a0 += sc[j0 + jj + 0] * vbase[(size_t)(j0 + jj + 0) * DMODEL];
        a1 += sc[j0 + jj + 1] * vbase[(size_t)(j0 + jj + 1) * DMODEL];
        a2 += sc[j0 + jj + 2] * vbase[(size_t)(j0 + jj + 2) * DMODEL];
        a3 += sc[j0 + jj + 3] * vbase[(size_t)(j0 + jj + 3) * DMODEL];
    }
    float acc = ((a0 + a1) + (a2 + a3)) * inv;
    __syncthreads();              // everyone has read red[0] before reuse
    red[t] = acc;
    __syncthreads();
    if (t < 64)
        o[rowq + t] = red[t] + red[t + 64] + red[t + 128] + red[t + 192];
}

// ---------------- MoE routing ----------------
__global__ void reset_kernel() { if (threadIdx.x < NE) g_cnt[threadIdx.x] = 0; }

__global__ void route_kernel(const float* __restrict__ z, const float* __restrict__ gw,
                             const float* __restrict__ gb)
{
    __shared__ float lg[NE];
    int tok = blockIdx.x;
    int lane = threadIdx.x & 31, e = threadIdx.x >> 5;   // 8 warps = 8 experts
    const float* zr = z + (size_t)tok * DMODEL;
    float s = 0.0f;
    for (int kk = lane; kk < DMODEL; kk += 32) s += zr[kk] * gw[kk * NE + e];
    #pragma unroll
    for (int off = 16; off > 0; off >>= 1) s += __shfl_down_sync(0xffffffffu, s, off);
    if (lane == 0) lg[e] = s + gb[e];
    __syncthreads();
    if (threadIdx.x == 0) {
        int i0 = 0; float v0 = lg[0];
        #pragma unroll
        for (int i = 1; i < NE; i++) if (lg[i] > v0) { v0 = lg[i]; i0 = i; }
        int i1 = -1; float v1 = -3.4e38f;
        #pragma unroll
        for (int i = 0; i < NE; i++) if (i != i0 && lg[i] > v1) { v1 = lg[i]; i1 = i; }
        float e1 = expf(v1 - v0);
        float invs = 1.0f / (1.0f + e1);
        float w0 = invs, w1 = e1 * invs;
        int p0 = atomicAdd(&g_cnt[i0], 1);
        g_ptok[i0 * MAXM + p0] = tok;
        g_pos[2 * tok] = i0 * MAXM + p0;
        g_wgt[2 * tok] = w0;
        int p1 = atomicAdd(&g_cnt[i1], 1);
        g_ptok[i1 * MAXM + p1] = tok;
        g_pos[2 * tok + 1] = i1 * MAXM + p1;
        g_wgt[2 * tok + 1] = w1;
    }
}

__global__ void combine_kernel()
{
    int tok = blockIdx.x, t = threadIdx.x;
    int p0 = g_pos[2 * tok], p1 = g_pos[2 * tok + 1];
    float w0 = g_wgt[2 * tok], w1 = g_wgt[2 * tok + 1];
    float4 a = ((const float4*)(g_y2 + (size_t)p0 * DMODEL))[t];
    float4 b = ((const float4*)(g_y2 + (size_t)p1 * DMODEL))[t];
    float4* f = (float4*)(g_feat + (size_t)tok * DMODEL);
    float4 fv = f[t];
    fv.x += w0 * a.x + w1 * b.x;
    fv.y += w0 * a.y + w1 * b.y;
    fv.z += w0 * a.z + w1 * b.z;
    fv.w += w0 * a.w + w1 * b.w;
    f[t] = fv;
}

// ---------------- host orchestration ----------------
extern "C" void kernel_launch(void* const* d_in, const int* in_sizes, int n_in,
                              void* d_out, int out_size)
{
    (void)in_sizes; (void)n_in; (void)out_size;
    const int*   et       = (const int*)d_in[0];
    const int*   xi       = (const int*)d_in[1];
    const int*   abt      = (const int*)d_in[2];
    const float* ent      = (const float*)d_in[3];
    const float* maskemb  = (const float*)d_in[4];
    const float* rel      = (const float*)d_in[5];
    const float* type     = (const float*)d_in[6];
    const float* bias_emb = (const float*)d_in[7];
    const float* ln1g     = (const float*)d_in[8];
    const float* ln1b     = (const float*)d_in[9];
    const float* wq       = (const float*)d_in[10];
    const float* bq       = (const float*)d_in[11];
    const float* wk       = (const float*)d_in[12];
    const float* bk       = (const float*)d_in[13];
    const float* wv       = (const float*)d_in[14];
    const float* bv       = (const float*)d_in[15];
    const float* wo       = (const float*)d_in[16];
    const float* bo       = (const float*)d_in[17];
    const float* ln2g     = (const float*)d_in[18];
    const float* ln2b     = (const float*)d_in[19];
    const float* gw       = (const float*)d_in[20];
    const float* gb       = (const float*)d_in[21];
    const float* w1       = (const float*)d_in[22];
    const float* b1       = (const float*)d_in[23];
    const float* w2       = (const float*)d_in[24];
    const float* b2       = (const float*)d_in[25];
    const float* flng     = (const float*)d_in[26];
    const float* flnb     = (const float*)d_in[27];
    float* out = (float*)d_out;

    float *feat, *xn, *qb, *kb, *vb, *ob, *hb, *yb;
    int *cntp, *ptokp;
    cudaGetSymbolAddress((void**)&feat,  g_feat);
    cudaGetSymbolAddress((void**)&xn,    g_xn);
    cudaGetSymbolAddress((void**)&qb,    g_q);
    cudaGetSymbolAddress((void**)&kb,    g_k);
    cudaGetSymbolAddress((void**)&vb,    g_v);
    cudaGetSymbolAddress((void**)&ob,    g_o);
    cudaGetSymbolAddress((void**)&hb,    g_h);
    cudaGetSymbolAddress((void**)&yb,    g_y2);
    cudaGetSymbolAddress((void**)&cntp,  g_cnt);
    cudaGetSymbolAddress((void**)&ptokp, g_ptok);

    embed_kernel<<<NTOK, 256>>>(et, xi, ent, maskemb, rel, type);

    dim3 gP(16, 16);         // 1024x1024 proj GEMMs
    dim3 gM1(32, 16, 8);     // expert N=2048
    dim3 gM2(16, 16, 8);     // expert N=1024

    for (int l = 0; l < 2; l++) {
        const size_t dd = (size_t)DMODEL * DMODEL;
        // 1) LN1
        ln_kernel<<<NTOK, 256>>>(feat, ln1g + l * DMODEL, ln1b + l * DMODEL, xn);
        // 2) q,k,v
        sgemm<false, false, false, false><<<gP, 256>>>(xn, wq + l * dd, bq + l * DMODEL, qb,
                                                       NTOK, DMODEL, DMODEL, 0, 0, 0, 0);
        sgemm<false, false, false, false><<<gP, 256>>>(xn, wk + l * dd, bk + l * DMODEL, kb,
                                                       NTOK, DMODEL, DMODEL, 0, 0, 0, 0);
        sgemm<false, false, false, false><<<gP, 256>>>(xn, wv + l * dd, bv + l * DMODEL, vb,
                                                       NTOK, DMODEL, DMODEL, 0, 0, 0, 0);
        // 3) attention
        attn_kernel<<<NB * NH * SEQ, 256>>>(qb, kb, vb, abt, bias_emb, ob);
        // 4) out proj + residual
        sgemm<false, true, false, false><<<gP, 256>>>(ob, wo + l * dd, bo + l * DMODEL, feat,
                                                      NTOK, DMODEL, DMODEL, 0, 0, 0, 0);
        // 5) LN2
        ln_kernel<<<NTOK, 256>>>(feat, ln2g + l * DMODEL, ln2b + l * DMODEL, xn);
        // 6) routing
        reset_kernel<<<1, 32>>>();
        route_kernel<<<NTOK, 256>>>(xn, gw + (size_t)l * DMODEL * NE, gb + l * NE);
        // 7) expert up-proj + relu (gathered rows of xn)
        sgemm<true, false, true, true><<<gM1, 256>>>(
            xn, w1 + (size_t)l * NE * DMODEL * DHID, b1 + (size_t)l * NE * DHID, hb,
            MAXM, DHID, DMODEL, ptokp, cntp, 0, (size_t)MAXM * DHID);
        // 8) expert down-proj
        sgemm<false, false, true, false><<<gM2, 256>>>(
            hb, w2 + (size_t)l * NE * DHID * DMODEL, b2 + (size_t)l * NE * DMODEL, yb,
            MAXM, DMODEL, DHID, 0, cntp, (size_t)MAXM * DHID, (size_t)MAXM * DMODEL);
        // 9) weighted combine into feat
        combine_kernel<<<NTOK, 256>>>();
    }

    // final layernorm -> out
    ln_kernel<<<NTOK, 256>>>(feat, flng, flnb, out);
}

// round 6
// speedup vs baseline: 1.6025x; 1.6025x over previous
#include <cuda_runtime.h>
#include <math.h>

// Problem constants
#define NTOK 1024      // B*S
#define DMODEL 1024
#define NH 16
#define HDIM 64
#define SEQ 256
#define NB 4
#define NE 8
#define DHID 2048
#define MAXM 1024      // max rows per expert

// ---------------- scratch (device globals; no allocation allowed) ----------------
__device__ float g_feat[NTOK * DMODEL];
__device__ float g_xn[NTOK * DMODEL];
__device__ float g_q[NTOK * DMODEL];
__device__ float g_k[NTOK * DMODEL];
__device__ float g_v[NTOK * DMODEL];
__device__ float g_o[NTOK * DMODEL];
__device__ float g_h[NE * MAXM * DHID];    // expert hidden
__device__ float g_y2[NE * MAXM * DMODEL]; // expert output
__device__ int   g_cnt[NE];
__device__ int   g_ptok[NE * MAXM];
__device__ int   g_pos[NTOK * 2];
__device__ float g_wgt[NTOK * 2];

// ---------------- embedding ----------------
__global__ void embed_kernel(const int* __restrict__ et, const int* __restrict__ xi,
                             const float* __restrict__ ent, const float* __restrict__ maskemb,
                             const float* __restrict__ rel, const float* __restrict__ type)
{
    int tok = blockIdx.x, t = threadIdx.x;   // 256 threads, 1 float4 each
    int ty = et[tok];
    int xv = xi[tok];
    const float* src;
    if (ty == 0)      src = ent + (size_t)(((unsigned)xv) % 40000u) * DMODEL;
    else if (ty == 1) src = maskemb;
    else              src = rel + (size_t)(((unsigned)xv) % 1000u) * DMODEL;
    float4 s4 = ((const float4*)src)[t];
    float4 t4 = ((const float4*)(type + (size_t)ty * DMODEL))[t];
    float4 r = make_float4(s4.x + t4.x, s4.y + t4.y, s4.z + t4.z, s4.w + t4.w);
    ((float4*)(g_feat + (size_t)tok * DMODEL))[t] = r;
}

// ---------------- layernorm ----------------
__global__ void ln_kernel(const float* __restrict__ x, const float* __restrict__ g,
                          const float* __restrict__ b, float* __restrict__ y)
{
    __shared__ float red[256];
    int row = blockIdx.x, t = threadIdx.x;
    float4 xv = ((const float4*)(x + (size_t)row * DMODEL))[t];
    red[t] = xv.x + xv.y + xv.z + xv.w;
    __syncthreads();
    #pragma unroll
    for (int off = 128; off > 0; off >>= 1) { if (t < off) red[t] += red[t + off]; __syncthreads(); }
    float m = red[0] * (1.0f / DMODEL);
    __syncthreads();
    float dx = xv.x - m, dy = xv.y - m, dz = xv.z - m, dw = xv.w - m;
    red[t] = dx * dx + dy * dy + dz * dz + dw * dw;
    __syncthreads();
    #pragma unroll
    for (int off = 128; off > 0; off >>= 1) { if (t < off) red[t] += red[t + off]; __syncthreads(); }
    float rs = rsqrtf(red[0] * (1.0f / DMODEL) + 1e-5f);
    float4 gv = ((const float4*)g)[t];
    float4 bv = ((const float4*)b)[t];
    float4 o = make_float4(dx * rs * gv.x + bv.x, dy * rs * gv.y + bv.y,
                           dz * rs * gv.z + bv.z, dw * rs * gv.w + bv.w);
    ((float4*)(y + (size_t)row * DMODEL))[t] = o;
}

// ---------------- TF32 tensor-core GEMM ----------------
// C[M,N] (+)= op(A[M,K] @ W[K,N] + bias[N])
// Block tile 128x64, BK=16, 256 threads (8 warps), warp tile 64x16 via m16n8k8.
// QKV: blockIdx.z in {0,1,2} selects (W,bias,C) triple.
// EXPERT: blockIdx.z selects expert; M from cnt[e]; W/bias/C offset per expert.
// GATHER: A rows indirect through gather[e*MAXM + m].
#define LDA 20
#define LDB 72

__device__ __forceinline__ unsigned f2tf(float f) {
    unsigned u; asm("cvt.rna.tf32.f32 %0, %1;" : "=r"(u) : "f"(f)); return u;
}

template<int RELU, int ACCUM, int EXPERT, int GATHER, int QKV>
__global__ void __launch_bounds__(256)
tgemm(const float* __restrict__ A,
      const float* __restrict__ W0, const float* __restrict__ Wx1, const float* __restrict__ Wx2,
      const float* __restrict__ B0, const float* __restrict__ Bx1, const float* __restrict__ Bx2,
      float* __restrict__ C0, float* __restrict__ Cx1, float* __restrict__ Cx2,
      int M, int N, int K,
      const int* __restrict__ gather, const int* __restrict__ cnt,
      size_t aStride, size_t cStride)
{
    __shared__ unsigned As[2][128 * LDA];
    __shared__ unsigned Bs[2][16 * LDB];

    int e = EXPERT ? blockIdx.z : 0;
    int Mloc = EXPERT ? cnt[e] : M;
    int mBase = blockIdx.y * 128;
    if (mBase >= Mloc) return;
    int nBase = blockIdx.x * 64;

    const float* W = W0; const float* bias = B0; float* C = C0;
    if (QKV) {
        int z = blockIdx.z;
        if (z == 1)      { W = Wx1; bias = Bx1; C = Cx1; }
        else if (z == 2) { W = Wx2; bias = Bx2; C = Cx2; }
    }
    const float* Ap = A;
    if (EXPERT) {
        W = W0 + (size_t)e * K * N;
        bias = B0 + (size_t)e * N;
        C = C0 + (size_t)e * cStride;
        if (!GATHER) Ap = A + (size_t)e * aStride;
    }

    int tid = threadIdx.x;
    int lane = tid & 31, warp = tid >> 5;
    int wM = (warp & 1) * 64;       // warp M offset within block tile
    int wN = (warp >> 1) * 16;      // warp N offset
    int g = lane >> 2, t = lane & 3;

    // global A staging: two rows per thread, one float4 along k each
    int r0 = tid >> 2;              // 0..63
    int r1 = r0 + 64;
    int ac4 = (tid & 3) * 4;
    int m0 = mBase + r0; m0 = m0 < Mloc ? m0 : Mloc - 1;
    int m1 = mBase + r1; m1 = m1 < Mloc ? m1 : Mloc - 1;
    int ar0 = GATHER ? gather[e * MAXM + m0] : m0;
    int ar1 = GATHER ? gather[e * MAXM + m1] : m1;
    const float* pA0 = Ap + (size_t)ar0 * K + ac4;
    const float* pA1 = Ap + (size_t)ar1 * K + ac4;

    // global B staging: 16 x 64 tile, one float4 per thread
    int br  = tid >> 4;             // 0..15
    int bc4 = (tid & 15) * 4;
    const float* pB = W + (size_t)br * N + nBase + bc4;

    float acc[4][2][4];
    #pragma unroll
    for (int i = 0; i < 4; i++)
        #pragma unroll
        for (int j = 0; j < 2; j++)
            #pragma unroll
            for (int q = 0; q < 4; q++) acc[i][j][q] = 0.0f;

    float4 sa0 = *(const float4*)pA0;
    float4 sa1 = *(const float4*)pA1;
    float4 sb  = *(const float4*)pB;

    int buf = 0;
    for (int k0 = 0; k0 < K; k0 += 16) {
        unsigned* As_ = As[buf];
        unsigned* Bs_ = Bs[buf];
        As_[r0 * LDA + ac4 + 0] = f2tf(sa0.x);
        As_[r0 * LDA + ac4 + 1] = f2tf(sa0.y);
        As_[r0 * LDA + ac4 + 2] = f2tf(sa0.z);
        As_[r0 * LDA + ac4 + 3] = f2tf(sa0.w);
        As_[r1 * LDA + ac4 + 0] = f2tf(sa1.x);
        As_[r1 * LDA + ac4 + 1] = f2tf(sa1.y);
        As_[r1 * LDA + ac4 + 2] = f2tf(sa1.z);
        As_[r1 * LDA + ac4 + 3] = f2tf(sa1.w);
        Bs_[br * LDB + bc4 + 0] = f2tf(sb.x);
        Bs_[br * LDB + bc4 + 1] = f2tf(sb.y);
        Bs_[br * LDB + bc4 + 2] = f2tf(sb.z);
        Bs_[br * LDB + bc4 + 3] = f2tf(sb.w);
        __syncthreads();

        if (k0 + 16 < K) {
            sa0 = *(const float4*)(pA0 + k0 + 16);
            sa1 = *(const float4*)(pA1 + k0 + 16);
            sb  = *(const float4*)(pB + (size_t)(k0 + 16) * N);
        }

        #pragma unroll
        for (int ks = 0; ks < 2; ks++) {
            unsigned af[4][4], bf[2][2];
            #pragma unroll
            for (int mt = 0; mt < 4; mt++) {
                int base = (wM + mt * 16 + g) * LDA + ks * 8 + t;
                af[mt][0] = As_[base];
                af[mt][1] = As_[base + 8 * LDA];
                af[mt][2] = As_[base + 4];
                af[mt][3] = As_[base + 8 * LDA + 4];
            }
            #pragma unroll
            for (int nt = 0; nt < 2; nt++) {
                int base = (ks * 8 + t) * LDB + wN + nt * 8 + g;
                bf[nt][0] = Bs_[base];
                bf[nt][1] = Bs_[base + 4 * LDB];
            }
            #pragma unroll
            for (int mt = 0; mt < 4; mt++)
                #pragma unroll
                for (int nt = 0; nt < 2; nt++)
                    asm volatile(
                        "mma.sync.aligned.m16n8k8.row.col.f32.tf32.tf32.f32 "
                        "{%0,%1,%2,%3}, {%4,%5,%6,%7}, {%8,%9}, {%0,%1,%2,%3};"
                        : "+f"(acc[mt][nt][0]), "+f"(acc[mt][nt][1]),
                          "+f"(acc[mt][nt][2]), "+f"(acc[mt][nt][3])
                        : "r"(af[mt][0]), "r"(af[mt][1]), "r"(af[mt][2]), "r"(af[mt][3]),
                          "r"(bf[nt][0]), "r"(bf[nt][1]));
        }
        buf ^= 1;
    }

    // epilogue: c0=(g,2t), c1=(g,2t+1), c2=(g+8,2t), c3=(g+8,2t+1)
    #pragma unroll
    for (int mt = 0; mt < 4; mt++) {
        #pragma unroll
        for (int half = 0; half < 2; half++) {
            int r = mBase + wM + mt * 16 + g + half * 8;
            if (r < Mloc) {
                #pragma unroll
                for (int nt = 0; nt < 2; nt++) {
                    int col = nBase + wN + nt * 8 + 2 * t;
                    float* cp = C + (size_t)r * N + col;
                    float v0 = acc[mt][nt][half * 2 + 0] + bias[col];
                    float v1 = acc[mt][nt][half * 2 + 1] + bias[col + 1];
                    if (RELU) { v0 = fmaxf(v0, 0.0f); v1 = fmaxf(v1, 0.0f); }
                    if (ACCUM) { cp[0] += v0; cp[1] += v1; }
                    else       { cp[0] = v0;  cp[1] = v1; }
                }
            }
        }
    }
}

// ---------------- attention: block per (b,h,i); 256 threads ----------------
__global__ void __launch_bounds__(256)
attn_kernel(const float* __restrict__ q, const float* __restrict__ k,
            const float* __restrict__ v, const int* __restrict__ abt,
            const float* __restrict__ bias_emb, float* __restrict__ o)
{
    __shared__ float qs[HDIM];
    __shared__ float sc[SEQ];
    __shared__ float red[256];
    int bid = blockIdx.x;
    int i = bid & 255;
    int h = (bid >> 8) & 15;
    int b = bid >> 12;
    int t = threadIdx.x;

    int rowq = (b * SEQ + i) * DMODEL + h * HDIM;
    if (t < HDIM) qs[t] = q[rowq + t];
    __syncthreads();

    int j = t;
    const float4* kr = (const float4*)(k + (size_t)(b * SEQ + j) * DMODEL + h * HDIM);
    float dot = 0.0f;
    #pragma unroll
    for (int d4 = 0; d4 < 16; d4++) {
        float4 kv = kr[d4];
        dot += qs[d4 * 4 + 0] * kv.x + qs[d4 * 4 + 1] * kv.y
             + qs[d4 * 4 + 2] * kv.z + qs[d4 * 4 + 3] * kv.w;
    }
    float bi = bias_emb[abt[(size_t)(b * SEQ + i) * SEQ + j] * NH + h];
    float s = dot * 0.125f + bi;

    red[t] = s; __syncthreads();
    #pragma unroll
    for (int off = 128; off > 0; off >>= 1) { if (t < off) red[t] = fmaxf(red[t], red[t + off]); __syncthreads(); }
    float mx = red[0];
    __syncthreads();
    float p = expf(s - mx);
    red[t] = p; sc[t] = p;
    __syncthreads();
    #pragma unroll
    for (int off = 128; off > 0; off >>= 1) { if (t < off) red[t] += red[t + off]; __syncthreads(); }
    float inv = 1.0f / red[0];

    int d = t & 63, grp = t >> 6;
    const float* vbase = v + (size_t)b * SEQ * DMODEL + h * HDIM + d;
    float a0 = 0, a1 = 0, a2 = 0, a3 = 0;
    int j0 = grp * 64;
    #pragma unroll 4
    for (int jj = 0; jj < 64; jj += 4) {
        a0 += sc[j0 + jj + 0] * vbase[(size_t)(j0 + jj + 0) * DMODEL];
        a1 += sc[j0 + jj + 1] * vbase[(size_t)(j0 + jj + 1) * DMODEL];
        a2 += sc[j0 + jj + 2] * vbase[(size_t)(j0 + jj + 2) * DMODEL];
        a3 += sc[j0 + jj + 3] * vbase[(size_t)(j0 + jj + 3) * DMODEL];
    }
    float acc = ((a0 + a1) + (a2 + a3)) * inv;
    __syncthreads();
    red[t] = acc;
    __syncthreads();
    if (t < 64)
        o[rowq + t] = red[t] + red[t + 64] + red[t + 128] + red[t + 192];
}

// ---------------- MoE routing ----------------
__global__ void reset_kernel() { if (threadIdx.x < NE) g_cnt[threadIdx.x] = 0; }

__global__ void route_kernel(const float* __restrict__ z, const float* __restrict__ gw,
                             const float* __restrict__ gb)
{
    __shared__ float lg[NE];
    int tok = blockIdx.x;
    int lane = threadIdx.x & 31, e = threadIdx.x >> 5;   // 8 warps = 8 experts
    const float* zr = z + (size_t)tok * DMODEL;
    float s = 0.0f;
    for (int kk = lane; kk < DMODEL; kk += 32) s += zr[kk] * gw[kk * NE + e];
    #pragma unroll
    for (int off = 16; off > 0; off >>= 1) s += __shfl_down_sync(0xffffffffu, s, off);
    if (lane == 0) lg[e] = s + gb[e];
    __syncthreads();
    if (threadIdx.x == 0) {
        int i0 = 0; float v0 = lg[0];
        #pragma unroll
        for (int i = 1; i < NE; i++) if (lg[i] > v0) { v0 = lg[i]; i0 = i; }
        int i1 = -1; float v1 = -3.4e38f;
        #pragma unroll
        for (int i = 0; i < NE; i++) if (i != i0 && lg[i] > v1) { v1 = lg[i]; i1 = i; }
        float e1 = expf(v1 - v0);
        float invs = 1.0f / (1.0f + e1);
        float w0 = invs, w1 = e1 * invs;
        int p0 = atomicAdd(&g_cnt[i0], 1);
        g_ptok[i0 * MAXM + p0] = tok;
        g_pos[2 * tok] = i0 * MAXM + p0;
        g_wgt[2 * tok] = w0;
        int p1 = atomicAdd(&g_cnt[i1], 1);
        g_ptok[i1 * MAXM + p1] = tok;
        g_pos[2 * tok + 1] = i1 * MAXM + p1;
        g_wgt[2 * tok + 1] = w1;
    }
}

__global__ void combine_kernel()
{
    int tok = blockIdx.x, t = threadIdx.x;
    int p0 = g_pos[2 * tok], p1 = g_pos[2 * tok + 1];
    float w0 = g_wgt[2 * tok], w1 = g_wgt[2 * tok + 1];
    float4 a = ((const float4*)(g_y2 + (size_t)p0 * DMODEL))[t];
    float4 b = ((const float4*)(g_y2 + (size_t)p1 * DMODEL))[t];
    float4* f = (float4*)(g_feat + (size_t)tok * DMODEL);
    float4 fv = f[t];
    fv.x += w0 * a.x + w1 * b.x;
    fv.y += w0 * a.y + w1 * b.y;
    fv.z += w0 * a.z + w1 * b.z;
    fv.w += w0 * a.w + w1 * b.w;
    f[t] = fv;
}

// ---------------- host orchestration ----------------
extern "C" void kernel_launch(void* const* d_in, const int* in_sizes, int n_in,
                              void* d_out, int out_size)
{
    (void)in_sizes; (void)n_in; (void)out_size;
    const int*   et       = (const int*)d_in[0];
    const int*   xi       = (const int*)d_in[1];
    const int*   abt      = (const int*)d_in[2];
    const float* ent      = (const float*)d_in[3];
    const float* maskemb  = (const float*)d_in[4];
    const float* rel      = (const float*)d_in[5];
    const float* type     = (const float*)d_in[6];
    const float* bias_emb = (const float*)d_in[7];
    const float* ln1g     = (const float*)d_in[8];
    const float* ln1b     = (const float*)d_in[9];
    const float* wq       = (const float*)d_in[10];
    const float* bq       = (const float*)d_in[11];
    const float* wk       = (const float*)d_in[12];
    const float* bk       = (const float*)d_in[13];
    const float* wv       = (const float*)d_in[14];
    const float* bv       = (const float*)d_in[15];
    const float* wo       = (const float*)d_in[16];
    const float* bo       = (const float*)d_in[17];
    const float* ln2g     = (const float*)d_in[18];
    const float* ln2b     = (const float*)d_in[19];
    const float* gw       = (const float*)d_in[20];
    const float* gb       = (const float*)d_in[21];
    const float* w1       = (const float*)d_in[22];
    const float* b1       = (const float*)d_in[23];
    const float* w2       = (const float*)d_in[24];
    const float* b2       = (const float*)d_in[25];
    const float* flng     = (const float*)d_in[26];
    const float* flnb     = (const float*)d_in[27];
    float* out = (float*)d_out;

    float *feat, *xn, *qb2, *kb2, *vb2, *ob, *hb, *yb;
    int *cntp, *ptokp;
    cudaGetSymbolAddress((void**)&feat,  g_feat);
    cudaGetSymbolAddress((void**)&xn,    g_xn);
    cudaGetSymbolAddress((void**)&qb2,   g_q);
    cudaGetSymbolAddress((void**)&kb2,   g_k);
    cudaGetSymbolAddress((void**)&vb2,   g_v);
    cudaGetSymbolAddress((void**)&ob,    g_o);
    cudaGetSymbolAddress((void**)&hb,    g_h);
    cudaGetSymbolAddress((void**)&yb,    g_y2);
    cudaGetSymbolAddress((void**)&cntp,  g_cnt);
    cudaGetSymbolAddress((void**)&ptokp, g_ptok);

    embed_kernel<<<NTOK, 256>>>(et, xi, ent, maskemb, rel, type);

    for (int l = 0; l < 2; l++) {
        const size_t dd = (size_t)DMODEL * DMODEL;
        // 1) LN1
        ln_kernel<<<NTOK, 256>>>(feat, ln1g + l * DMODEL, ln1b + l * DMODEL, xn);
        // 2) fused q,k,v projections (grid.z selects triple)
        tgemm<0,0,0,0,1><<<dim3(16, 8, 3), 256>>>(
            xn, wq + l * dd, wk + l * dd, wv + l * dd,
            bq + l * DMODEL, bk + l * DMODEL, bv + l * DMODEL,
            qb2, kb2, vb2,
            NTOK, DMODEL, DMODEL, (const int*)0, (const int*)0, 0, 0);
        // 3) attention
        attn_kernel<<<NB * NH * SEQ, 256>>>(qb2, kb2, vb2, abt, bias_emb, ob);
        // 4) out proj + residual accumulate
        tgemm<0,1,0,0,0><<<dim3(16, 8), 256>>>(
            ob, wo + l * dd, (const float*)0, (const float*)0,
            bo + l * DMODEL, (const float*)0, (const float*)0,
            feat, (float*)0, (float*)0,
            NTOK, DMODEL, DMODEL, (const int*)0, (const int*)0, 0, 0);
        // 5) LN2
        ln_kernel<<<NTOK, 256>>>(feat, ln2g + l * DMODEL, ln2b + l * DMODEL, xn);
        // 6) routing
        reset_kernel<<<1, 32>>>();
        route_kernel<<<NTOK, 256>>>(xn, gw + (size_t)l * DMODEL * NE, gb + l * NE);
        // 7) expert up-proj + relu (gathered rows of xn)
        tgemm<1,0,1,1,0><<<dim3(32, 8, 8), 256>>>(
            xn, w1 + (size_t)l * NE * DMODEL * DHID, (const float*)0, (const float*)0,
            b1 + (size_t)l * NE * DHID, (const float*)0, (const float*)0,
            hb, (float*)0, (float*)0,
            MAXM, DHID, DMODEL, ptokp, cntp, 0, (size_t)MAXM * DHID);
        // 8) expert down-proj
        tgemm<0,0,1,0,0><<<dim3(16, 8, 8), 256>>>(
            hb, w2 + (size_t)l * NE * DHID * DMODEL, (const float*)0, (const float*)0,
            b2 + (size_t)l * NE * DMODEL, (const float*)0, (const float*)0,
            yb, (float*)0, (float*)0,
            MAXM, DMODEL, DHID, (const int*)0, cntp, (size_t)MAXM * DHID, (size_t)MAXM * DMODEL);
        // 9) weighted combine into feat
        combine_kernel<<<NTOK, 256>>>();
    }

    // final layernorm -> out
    ln_kernel<<<NTOK, 256>>>(feat, flng, flnb, out);
}

// round 9
// speedup vs baseline: 2.2399x; 1.3977x over previous
#include <cuda_runtime.h>
#include <math.h>

// Problem constants
#define NTOK 1024      // B*S
#define DMODEL 1024
#define NH 16
#define HDIM 64
#define SEQ 256
#define NB 4
#define NE 8
#define DHID 2048
#define MAXM 1024      // max rows per expert

// ---------------- scratch (device globals; no allocation allowed) ----------------
__device__ float g_feat[NTOK * DMODEL];
__device__ float g_xn[NTOK * DMODEL];
__device__ float g_q[NTOK * DMODEL];
__device__ float g_k[NTOK * DMODEL];
__device__ float g_v[NTOK * DMODEL];
__device__ float g_o[NTOK * DMODEL];
__device__ float g_h[NE * MAXM * DHID];    // expert hidden
__device__ float g_y2[NE * MAXM * DMODEL]; // expert output
__device__ int   g_cnt[NE];
__device__ int   g_ptok[NE * MAXM];
__device__ int   g_pos[NTOK * 2];
__device__ float g_wgt[NTOK * 2];

// ---------------- embedding ----------------
__global__ void embed_kernel(const int* __restrict__ et, const int* __restrict__ xi,
                             const float* __restrict__ ent, const float* __restrict__ maskemb,
                             const float* __restrict__ rel, const float* __restrict__ type)
{
    int tok = blockIdx.x, t = threadIdx.x;   // 256 threads, 1 float4 each
    int ty = et[tok];
    int xv = xi[tok];
    const float* src;
    if (ty == 0)      src = ent + (size_t)(((unsigned)xv) % 40000u) * DMODEL;
    else if (ty == 1) src = maskemb;
    else              src = rel + (size_t)(((unsigned)xv) % 1000u) * DMODEL;
    float4 s4 = ((const float4*)src)[t];
    float4 t4 = ((const float4*)(type + (size_t)ty * DMODEL))[t];
    float4 r = make_float4(s4.x + t4.x, s4.y + t4.y, s4.z + t4.z, s4.w + t4.w);
    ((float4*)(g_feat + (size_t)tok * DMODEL))[t] = r;
}

// ---------------- layernorm ----------------
__global__ void ln_kernel(const float* __restrict__ x, const float* __restrict__ g,
                          const float* __restrict__ b, float* __restrict__ y)
{
    __shared__ float red[256];
    int row = blockIdx.x, t = threadIdx.x;
    float4 xv = ((const float4*)(x + (size_t)row * DMODEL))[t];
    red[t] = xv.x + xv.y + xv.z + xv.w;
    __syncthreads();
    #pragma unroll
    for (int off = 128; off > 0; off >>= 1) { if (t < off) red[t] += red[t + off]; __syncthreads(); }
    float m = red[0] * (1.0f / DMODEL);
    __syncthreads();
    float dx = xv.x - m, dy = xv.y - m, dz = xv.z - m, dw = xv.w - m;
    red[t] = dx * dx + dy * dy + dz * dz + dw * dw;
    __syncthreads();
    #pragma unroll
    for (int off = 128; off > 0; off >>= 1) { if (t < off) red[t] += red[t + off]; __syncthreads(); }
    float rs = rsqrtf(red[0] * (1.0f / DMODEL) + 1e-5f);
    float4 gv = ((const float4*)g)[t];
    float4 bv = ((const float4*)b)[t];
    float4 o = make_float4(dx * rs * gv.x + bv.x, dy * rs * gv.y + bv.y,
                           dz * rs * gv.z + bv.z, dw * rs * gv.w + bv.w);
    ((float4*)(y + (size_t)row * DMODEL))[t] = o;
}

// ---------------- TF32 tensor-core GEMM ----------------
#define LDA 20
#define LDB 72

__device__ __forceinline__ unsigned f2tf(float f) {
    unsigned u; asm("cvt.rna.tf32.f32 %0, %1;" : "=r"(u) : "f"(f)); return u;
}

template<int RELU, int ACCUM, int EXPERT, int GATHER, int QKV>
__global__ void __launch_bounds__(256)
tgemm(const float* __restrict__ A,
      const float* __restrict__ W0, const float* __restrict__ Wx1, const float* __restrict__ Wx2,
      const float* __restrict__ B0, const float* __restrict__ Bx1, const float* __restrict__ Bx2,
      float* __restrict__ C0, float* __restrict__ Cx1, float* __restrict__ Cx2,
      int M, int N, int K,
      const int* __restrict__ gather, const int* __restrict__ cnt,
      size_t aStride, size_t cStride)
{
    __shared__ unsigned As[2][128 * LDA];
    __shared__ unsigned Bs[2][16 * LDB];

    int e = EXPERT ? blockIdx.z : 0;
    int Mloc = EXPERT ? cnt[e] : M;
    int mBase = blockIdx.y * 128;
    if (mBase >= Mloc) return;
    int nBase = blockIdx.x * 64;

    const float* W = W0; const float* bias = B0; float* C = C0;
    if (QKV) {
        int z = blockIdx.z;
        if (z == 1)      { W = Wx1; bias = Bx1; C = Cx1; }
        else if (z == 2) { W = Wx2; bias = Bx2; C = Cx2; }
    }
    const float* Ap = A;
    if (EXPERT) {
        W = W0 + (size_t)e * K * N;
        bias = B0 + (size_t)e * N;
        C = C0 + (size_t)e * cStride;
        if (!GATHER) Ap = A + (size_t)e * aStride;
    }

    int tid = threadIdx.x;
    int lane = tid & 31, warp = tid >> 5;
    int wM = (warp & 1) * 64;
    int wN = (warp >> 1) * 16;
    int g = lane >> 2, t = lane & 3;

    int r0 = tid >> 2;
    int r1 = r0 + 64;
    int ac4 = (tid & 3) * 4;
    int m0 = mBase + r0; m0 = m0 < Mloc ? m0 : Mloc - 1;
    int m1 = mBase + r1; m1 = m1 < Mloc ? m1 : Mloc - 1;
    int ar0 = GATHER ? gather[e * MAXM + m0] : m0;
    int ar1 = GATHER ? gather[e * MAXM + m1] : m1;
    const float* pA0 = Ap + (size_t)ar0 * K + ac4;
    const float* pA1 = Ap + (size_t)ar1 * K + ac4;

    int br  = tid >> 4;
    int bc4 = (tid & 15) * 4;
    const float* pB = W + (size_t)br * N + nBase + bc4;

    float acc[4][2][4];
    #pragma unroll
    for (int i = 0; i < 4; i++)
        #pragma unroll
        for (int j = 0; j < 2; j++)
            #pragma unroll
            for (int q = 0; q < 4; q++) acc[i][j][q] = 0.0f;

    float4 sa0 = *(const float4*)pA0;
    float4 sa1 = *(const float4*)pA1;
    float4 sb  = *(const float4*)pB;

    int buf = 0;
    for (int k0 = 0; k0 < K; k0 += 16) {
        unsigned* As_ = As[buf];
        unsigned* Bs_ = Bs[buf];
        As_[r0 * LDA + ac4 + 0] = f2tf(sa0.x);
        As_[r0 * LDA + ac4 + 1] = f2tf(sa0.y);
        As_[r0 * LDA + ac4 + 2] = f2tf(sa0.z);
        As_[r0 * LDA + ac4 + 3] = f2tf(sa0.w);
        As_[r1 * LDA + ac4 + 0] = f2tf(sa1.x);
        As_[r1 * LDA + ac4 + 1] = f2tf(sa1.y);
        As_[r1 * LDA + ac4 + 2] = f2tf(sa1.z);
        As_[r1 * LDA + ac4 + 3] = f2tf(sa1.w);
        Bs_[br * LDB + bc4 + 0] = f2tf(sb.x);
        Bs_[br * LDB + bc4 + 1] = f2tf(sb.y);
        Bs_[br * LDB + bc4 + 2] = f2tf(sb.z);
        Bs_[br * LDB + bc4 + 3] = f2tf(sb.w);
        __syncthreads();

        if (k0 + 16 < K) {
            sa0 = *(const float4*)(pA0 + k0 + 16);
            sa1 = *(const float4*)(pA1 + k0 + 16);
            sb  = *(const float4*)(pB + (size_t)(k0 + 16) * N);
        }

        #pragma unroll
        for (int ks = 0; ks < 2; ks++) {
            unsigned af[4][4], bf[2][2];
            #pragma unroll
            for (int mt = 0; mt < 4; mt++) {
                int base = (wM + mt * 16 + g) * LDA + ks * 8 + t;
                af[mt][0] = As_[base];
                af[mt][1] = As_[base + 8 * LDA];
                af[mt][2] = As_[base + 4];
                af[mt][3] = As_[base + 8 * LDA + 4];
            }
            #pragma unroll
            for (int nt = 0; nt < 2; nt++) {
                int base = (ks * 8 + t) * LDB + wN + nt * 8 + g;
                bf[nt][0] = Bs_[base];
                bf[nt][1] = Bs_[base + 4 * LDB];
            }
            #pragma unroll
            for (int mt = 0; mt < 4; mt++)
                #pragma unroll
                for (int nt = 0; nt < 2; nt++)
                    asm volatile(
                        "mma.sync.aligned.m16n8k8.row.col.f32.tf32.tf32.f32 "
                        "{%0,%1,%2,%3}, {%4,%5,%6,%7}, {%8,%9}, {%0,%1,%2,%3};"
                        : "+f"(acc[mt][nt][0]), "+f"(acc[mt][nt][1]),
                          "+f"(acc[mt][nt][2]), "+f"(acc[mt][nt][3])
                        : "r"(af[mt][0]), "r"(af[mt][1]), "r"(af[mt][2]), "r"(af[mt][3]),
                          "r"(bf[nt][0]), "r"(bf[nt][1]));
        }
        buf ^= 1;
    }

    #pragma unroll
    for (int mt = 0; mt < 4; mt++) {
        #pragma unroll
        for (int half = 0; half < 2; half++) {
            int r = mBase + wM + mt * 16 + g + half * 8;
            if (r < Mloc) {
                #pragma unroll
                for (int nt = 0; nt < 2; nt++) {
                    int col = nBase + wN + nt * 8 + 2 * t;
                    float* cp = C + (size_t)r * N + col;
                    float v0 = acc[mt][nt][half * 2 + 0] + bias[col];
                    float v1 = acc[mt][nt][half * 2 + 1] + bias[col + 1];
                    if (RELU) { v0 = fmaxf(v0, 0.0f); v1 = fmaxf(v1, 0.0f); }
                    if (ACCUM) { cp[0] += v0; cp[1] += v1; }
                    else       { cp[0] = v0;  cp[1] = v1; }
                }
            }
        }
    }
}

// ---------------- tiled attention ----------------
// Block = (b, h, 32-query tile); 256 threads; smem-staged K/V tiles (coalesced),
// conflict-free LDS fragments, warp-shuffle softmax, fp32 throughout.
#define QT 32
#define KT 64
#define KVP 68                 // K/V smem row pitch (floats)
#define SCP 260                // score row pitch (floats, mult of 4)
#define ATTN_SMEM ((QT*KVP + KT*KVP + QT*SCP) * 4)

__global__ void __launch_bounds__(256)
attn2_kernel(const float* __restrict__ q, const float* __restrict__ k,
             const float* __restrict__ v, const int* __restrict__ abt,
             const float* __restrict__ bias_emb, float* __restrict__ o)
{
    extern __shared__ float sm[];
    float* Qs  = sm;                 // [QT][KVP]
    float* KVs = sm + QT * KVP;      // [KT][KVP]
    float* Sc  = KVs + KT * KVP;     // [QT][SCP]

    int bid = blockIdx.x;
    int qt = bid & 7, h = (bid >> 3) & 15, b = bid >> 7;
    int q0 = qt * QT;
    int t = threadIdx.x;
    int lane = t & 31, warp = t >> 5;

    // load Q tile (scaled by 1/8): row = t>>3, 8 floats at (t&7)*8
    {
        int r = t >> 3, c = (t & 7) * 8;
        const float* qg = q + (size_t)(b * SEQ + q0 + r) * DMODEL + h * HDIM + c;
        float4 a0 = *(const float4*)qg;
        float4 a1 = *(const float4*)(qg + 4);
        float* dst = Qs + r * KVP + c;
        dst[0] = a0.x * 0.125f; dst[1] = a0.y * 0.125f; dst[2] = a0.z * 0.125f; dst[3] = a0.w * 0.125f;
        dst[4] = a1.x * 0.125f; dst[5] = a1.y * 0.125f; dst[6] = a1.z * 0.125f; dst[7] = a1.w * 0.125f;
    }
    __syncthreads();

    int qq = t >> 3;      // owned query row (0..31)
    int kk = t & 7;

    // -------- pass 1: scores --------
    for (int kt = 0; kt < 4; kt++) {
        int k0 = kt * KT;
        {   // coalesced K tile load: row = t>>2, 16 floats at (t&3)*16
            int r = t >> 2, c = (t & 3) * 16;
            const float* kg = k + (size_t)(b * SEQ + k0 + r) * DMODEL + h * HDIM + c;
            float4 x0 = *(const float4*)kg;
            float4 x1 = *(const float4*)(kg + 4);
            float4 x2 = *(const float4*)(kg + 8);
            float4 x3 = *(const float4*)(kg + 12);
            float* dst = KVs + r * KVP + c;
            *(float4*)(dst)      = x0;
            *(float4*)(dst + 4)  = x1;
            *(float4*)(dst + 8)  = x2;
            *(float4*)(dst + 12) = x3;
        }
        __syncthreads();

        float acc[8] = {0, 0, 0, 0, 0, 0, 0, 0};
        #pragma unroll
        for (int d4 = 0; d4 < 16; d4++) {
            float4 qv = *(const float4*)(Qs + qq * KVP + d4 * 4);
            #pragma unroll
            for (int j = 0; j < 8; j++) {
                float4 kv = *(const float4*)(KVs + (kk + 8 * j) * KVP + d4 * 4);
                acc[j] += qv.x * kv.x + qv.y * kv.y + qv.z * kv.z + qv.w * kv.w;
            }
        }
        const int* arow = abt + (size_t)(b * SEQ + q0 + qq) * SEQ + k0;
        #pragma unroll
        for (int j = 0; j < 8; j++) {
            int bt = arow[kk + 8 * j];
            Sc[qq * SCP + k0 + kk + 8 * j] = acc[j] + bias_emb[bt * NH + h];
        }
        __syncthreads();
    }

    // -------- softmax (4 rows per warp, shuffle reductions) --------
    #pragma unroll
    for (int rr = 0; rr < 4; rr++) {
        int r = warp * 4 + rr;
        float vals[8];
        float mx = -3.4e38f;
        #pragma unroll
        for (int c = 0; c < 8; c++) {
            vals[c] = Sc[r * SCP + lane + 32 * c];
            mx = fmaxf(mx, vals[c]);
        }
        #pragma unroll
        for (int off = 16; off > 0; off >>= 1)
            mx = fmaxf(mx, __shfl_xor_sync(0xffffffffu, mx, off));
        float s = 0.0f;
        #pragma unroll
        for (int c = 0; c < 8; c++) { vals[c] = expf(vals[c] - mx); s += vals[c]; }
        #pragma unroll
        for (int off = 16; off > 0; off >>= 1)
            s += __shfl_xor_sync(0xffffffffu, s, off);
        float inv = 1.0f / s;
        #pragma unroll
        for (int c = 0; c < 8; c++)
            Sc[r * SCP + lane + 32 * c] = vals[c] * inv;
    }
    __syncthreads();

    // -------- pass 2: PV --------
    int dh = t & 7;   // thread owns d-slices [4*dh,4*dh+4) and [32+4*dh, 32+4*dh+4)
    float4 o0 = make_float4(0, 0, 0, 0);
    float4 o1 = make_float4(0, 0, 0, 0);
    for (int kt = 0; kt < 4; kt++) {
        int k0 = kt * KT;
        {   // coalesced V tile load
            int r = t >> 2, c = (t & 3) * 16;
            const float* vg = v + (size_t)(b * SEQ + k0 + r) * DMODEL + h * HDIM + c;
            float4 x0 = *(const float4*)vg;
            float4 x1 = *(const float4*)(vg + 4);
            float4 x2 = *(const float4*)(vg + 8);
            float4 x3 = *(const float4*)(vg + 12);
            float* dst = KVs + r * KVP + c;
            *(float4*)(dst)      = x0;
            *(float4*)(dst + 4)  = x1;
            *(float4*)(dst + 8)  = x2;
            *(float4*)(dst + 12) = x3;
        }
        __syncthreads();

        const float* prow = Sc + qq * SCP + k0;
        #pragma unroll
        for (int j4 = 0; j4 < 16; j4++) {
            float4 p4 = *(const float4*)(prow + j4 * 4);
            float pr[4] = {p4.x, p4.y, p4.z, p4.w};
            #pragma unroll
            for (int u = 0; u < 4; u++) {
                int j = j4 * 4 + u;
                float4 va = *(const float4*)(KVs + j * KVP + dh * 4);
                float4 vb = *(const float4*)(KVs + j * KVP + (dh + 8) * 4);
                float p = pr[u];
                o0.x += p * va.x; o0.y += p * va.y; o0.z += p * va.z; o0.w += p * va.w;
                o1.x += p * vb.x; o1.y += p * vb.y; o1.z += p * vb.z; o1.w += p * vb.w;
            }
        }
        __syncthreads();
    }

    float* og = o + (size_t)(b * SEQ + q0 + qq) * DMODEL + h * HDIM;
    *(float4*)(og + dh * 4) = o0;
    *(float4*)(og + 32 + dh * 4) = o1;
}

// ---------------- MoE routing ----------------
__global__ void reset_kernel() { if (threadIdx.x < NE) g_cnt[threadIdx.x] = 0; }

__global__ void route_kernel(const float* __restrict__ z, const float* __restrict__ gw,
                             const float* __restrict__ gb)
{
    __shared__ float lg[NE];
    int tok = blockIdx.x;
    int lane = threadIdx.x & 31, e = threadIdx.x >> 5;
    const float* zr = z + (size_t)tok * DMODEL;
    float s = 0.0f;
    for (int kk = lane; kk < DMODEL; kk += 32) s += zr[kk] * gw[kk * NE + e];
    #pragma unroll
    for (int off = 16; off > 0; off >>= 1) s += __shfl_down_sync(0xffffffffu, s, off);
    if (lane == 0) lg[e] = s + gb[e];
    __syncthreads();
    if (threadIdx.x == 0) {
        int i0 = 0; float v0 = lg[0];
        #pragma unroll
        for (int i = 1; i < NE; i++) if (lg[i] > v0) { v0 = lg[i]; i0 = i; }
        int i1 = -1; float v1 = -3.4e38f;
        #pragma unroll
        for (int i = 0; i < NE; i++) if (i != i0 && lg[i] > v1) { v1 = lg[i]; i1 = i; }
        float e1 = expf(v1 - v0);
        float invs = 1.0f / (1.0f + e1);
        float w0 = invs, w1 = e1 * invs;
        int p0 = atomicAdd(&g_cnt[i0], 1);
        g_ptok[i0 * MAXM + p0] = tok;
        g_pos[2 * tok] = i0 * MAXM + p0;
        g_wgt[2 * tok] = w0;
        int p1 = atomicAdd(&g_cnt[i1], 1);
        g_ptok[i1 * MAXM + p1] = tok;
        g_pos[2 * tok + 1] = i1 * MAXM + p1;
        g_wgt[2 * tok + 1] = w1;
    }
}

__global__ void combine_kernel()
{
    int tok = blockIdx.x, t = threadIdx.x;
    int p0 = g_pos[2 * tok], p1 = g_pos[2 * tok + 1];
    float w0 = g_wgt[2 * tok], w1 = g_wgt[2 * tok + 1];
    float4 a = ((const float4*)(g_y2 + (size_t)p0 * DMODEL))[t];
    float4 b = ((const float4*)(g_y2 + (size_t)p1 * DMODEL))[t];
    float4* f = (float4*)(g_feat + (size_t)tok * DMODEL);
    float4 fv = f[t];
    fv.x += w0 * a.x + w1 * b.x;
    fv.y += w0 * a.y + w1 * b.y;
    fv.z += w0 * a.z + w1 * b.z;
    fv.w += w0 * a.w + w1 * b.w;
    f[t] = fv;
}

// ---------------- host orchestration ----------------
extern "C" void kernel_launch(void* const* d_in, const int* in_sizes, int n_in,
                              void* d_out, int out_size)
{
    (void)in_sizes; (void)n_in; (void)out_size;
    const int*   et       = (const int*)d_in[0];
    const int*   xi       = (const int*)d_in[1];
    const int*   abt      = (const int*)d_in[2];
    const float* ent      = (const float*)d_in[3];
    const float* maskemb  = (const float*)d_in[4];
    const float* rel      = (const float*)d_in[5];
    const float* type     = (const float*)d_in[6];
    const float* bias_emb = (const float*)d_in[7];
    const float* ln1g     = (const float*)d_in[8];
    const float* ln1b     = (const float*)d_in[9];
    const float* wq       = (const float*)d_in[10];
    const float* bq       = (const float*)d_in[11];
    const float* wk       = (const float*)d_in[12];
    const float* bk       = (const float*)d_in[13];
    const float* wv       = (const float*)d_in[14];
    const float* bv       = (const float*)d_in[15];
    const float* wo       = (const float*)d_in[16];
    const float* bo       = (const float*)d_in[17];
    const float* ln2g     = (const float*)d_in[18];
    const float* ln2b     = (const float*)d_in[19];
    const float* gw       = (const float*)d_in[20];
    const float* gb       = (const float*)d_in[21];
    const float* w1       = (const float*)d_in[22];
    const float* b1       = (const float*)d_in[23];
    const float* w2       = (const float*)d_in[24];
    const float* b2       = (const float*)d_in[25];
    const float* flng     = (const float*)d_in[26];
    const float* flnb     = (const float*)d_in[27];
    float* out = (float*)d_out;

    float *feat, *xn, *qb2, *kb2, *vb2, *ob, *hb, *yb;
    int *cntp, *ptokp;
    cudaGetSymbolAddress((void**)&feat,  g_feat);
    cudaGetSymbolAddress((void**)&xn,    g_xn);
    cudaGetSymbolAddress((void**)&qb2,   g_q);
    cudaGetSymbolAddress((void**)&kb2,   g_k);
    cudaGetSymbolAddress((void**)&vb2,   g_v);
    cudaGetSymbolAddress((void**)&ob,    g_o);
    cudaGetSymbolAddress((void**)&hb,    g_h);
    cudaGetSymbolAddress((void**)&yb,    g_y2);
    cudaGetSymbolAddress((void**)&cntp,  g_cnt);
    cudaGetSymbolAddress((void**)&ptokp, g_ptok);

    static int attn_attr_set = 0;
    if (!attn_attr_set) {
        cudaFuncSetAttribute(attn2_kernel,
                             cudaFuncAttributeMaxDynamicSharedMemorySize, ATTN_SMEM);
        attn_attr_set = 1;
    }

    embed_kernel<<<NTOK, 256>>>(et, xi, ent, maskemb, rel, type);

    for (int l = 0; l < 2; l++) {
        const size_t dd = (size_t)DMODEL * DMODEL;
        // 1) LN1
        ln_kernel<<<NTOK, 256>>>(feat, ln1g + l * DMODEL, ln1b + l * DMODEL, xn);
        // 2) fused q,k,v projections
        tgemm<0,0,0,0,1><<<dim3(16, 8, 3), 256>>>(
            xn, wq + l * dd, wk + l * dd, wv + l * dd,
            bq + l * DMODEL, bk + l * DMODEL, bv + l * DMODEL,
            qb2, kb2, vb2,
            NTOK, DMODEL, DMODEL, (const int*)0, (const int*)0, 0, 0);
        // 3) attention (tiled)
        attn2_kernel<<<NB * NH * (SEQ / QT), 256, ATTN_SMEM>>>(
            qb2, kb2, vb2, abt, bias_emb, ob);
        // 4) out proj + residual accumulate
        tgemm<0,1,0,0,0><<<dim3(16, 8), 256>>>(
            ob, wo + l * dd, (const float*)0, (const float*)0,
            bo + l * DMODEL, (const float*)0, (const float*)0,
            feat, (float*)0, (float*)0,
            NTOK, DMODEL, DMODEL, (const int*)0, (const int*)0, 0, 0);
        // 5) LN2
        ln_kernel<<<NTOK, 256>>>(feat, ln2g + l * DMODEL, ln2b + l * DMODEL, xn);
        // 6) routing
        reset_kernel<<<1, 32>>>();
        route_kernel<<<NTOK, 256>>>(xn, gw + (size_t)l * DMODEL * NE, gb + l * NE);
        // 7) expert up-proj + relu (gathered rows of xn)
        tgemm<1,0,1,1,0><<<dim3(32, 8, 8), 256>>>(
            xn, w1 + (size_t)l * NE * DMODEL * DHID, (const float*)0, (const float*)0,
            b1 + (size_t)l * NE * DHID, (const float*)0, (const float*)0,
            hb, (float*)0, (float*)0,
            MAXM, DHID, DMODEL, ptokp, cntp, 0, (size_t)MAXM * DHID);
        // 8) expert down-proj
        tgemm<0,0,1,0,0><<<dim3(16, 8, 8), 256>>>(
            hb, w2 + (size_t)l * NE * DHID * DMODEL, (const float*)0, (const float*)0,
            b2 + (size_t)l * NE * DMODEL, (const float*)0, (const float*)0,
            yb, (float*)0, (float*)0,
            MAXM, DMODEL, DHID, (const int*)0, cntp, (size_t)MAXM * DHID, (size_t)MAXM * DMODEL);
        // 9) weighted combine into feat
        combine_kernel<<<NTOK, 256>>>();
    }

    // final layernorm -> out
    ln_kernel<<<NTOK, 256>>>(feat, flng, flnb, out);
}

// round 10
// speedup vs baseline: 2.2555x; 1.0070x over previous
#include <cuda_runtime.h>
#include <math.h>

// Problem constants
#define NTOK 1024      // B*S
#define DMODEL 1024
#define NH 16
#define HDIM 64
#define SEQ 256
#define NB 4
#define NE 8
#define DHID 2048
#define MAXM 1024      // max rows per expert

// ---------------- scratch (device globals; no allocation allowed) ----------------
__device__ float g_feat[NTOK * DMODEL];
__device__ float g_xn[NTOK * DMODEL];     // exact LN output (route reads this)
__device__ float g_xnr[NTOK * DMODEL];    // tf32-rounded LN output (GEMM A)
__device__ float g_q[NTOK * DMODEL];
__device__ float g_k[NTOK * DMODEL];
__device__ float g_v[NTOK * DMODEL];
__device__ float g_o[NTOK * DMODEL];
__device__ float g_h[NE * MAXM * DHID];    // expert hidden (tf32-rounded)
__device__ float g_y2[NE * MAXM * DMODEL]; // expert output
__device__ int   g_cnt[NE];
__device__ int   g_ptok[NE * MAXM];
__device__ int   g_pos[NTOK * 2];
__device__ float g_wgt[NTOK * 2];

__device__ __forceinline__ unsigned f2tf(float f) {
    unsigned u; asm("cvt.rna.tf32.f32 %0, %1;" : "=r"(u) : "f"(f)); return u;
}
__device__ __forceinline__ float roundtf(float f) {
    return __uint_as_float(f2tf(f));
}

// ---------------- embedding ----------------
__global__ void embed_kernel(const int* __restrict__ et, const int* __restrict__ xi,
                             const float* __restrict__ ent, const float* __restrict__ maskemb,
                             const float* __restrict__ rel, const float* __restrict__ type)
{
    int tok = blockIdx.x, t = threadIdx.x;   // 256 threads, 1 float4 each
    int ty = et[tok];
    int xv = xi[tok];
    const float* src;
    if (ty == 0)      src = ent + (size_t)(((unsigned)xv) % 40000u) * DMODEL;
    else if (ty == 1) src = maskemb;
    else              src = rel + (size_t)(((unsigned)xv) % 1000u) * DMODEL;
    float4 s4 = ((const float4*)src)[t];
    float4 t4 = ((const float4*)(type + (size_t)ty * DMODEL))[t];
    float4 r = make_float4(s4.x + t4.x, s4.y + t4.y, s4.z + t4.z, s4.w + t4.w);
    ((float4*)(g_feat + (size_t)tok * DMODEL))[t] = r;
}

// ---------------- layernorm: writes exact y and tf32-rounded yr ----------------
__global__ void ln_kernel(const float* __restrict__ x, const float* __restrict__ g,
                          const float* __restrict__ b, float* __restrict__ y,
                          float* __restrict__ yr)
{
    __shared__ float red[256];
    int row = blockIdx.x, t = threadIdx.x;
    float4 xv = ((const float4*)(x + (size_t)row * DMODEL))[t];
    red[t] = xv.x + xv.y + xv.z + xv.w;
    __syncthreads();
    #pragma unroll
    for (int off = 128; off > 0; off >>= 1) { if (t < off) red[t] += red[t + off]; __syncthreads(); }
    float m = red[0] * (1.0f / DMODEL);
    __syncthreads();
    float dx = xv.x - m, dy = xv.y - m, dz = xv.z - m, dw = xv.w - m;
    red[t] = dx * dx + dy * dy + dz * dz + dw * dw;
    __syncthreads();
    #pragma unroll
    for (int off = 128; off > 0; off >>= 1) { if (t < off) red[t] += red[t + off]; __syncthreads(); }
    float rs = rsqrtf(red[0] * (1.0f / DMODEL) + 1e-5f);
    float4 gv = ((const float4*)g)[t];
    float4 bv = ((const float4*)b)[t];
    float4 o = make_float4(dx * rs * gv.x + bv.x, dy * rs * gv.y + bv.y,
                           dz * rs * gv.z + bv.z, dw * rs * gv.w + bv.w);
    ((float4*)(y + (size_t)row * DMODEL))[t] = o;
    float4 orr = make_float4(roundtf(o.x), roundtf(o.y), roundtf(o.z), roundtf(o.w));
    ((float4*)(yr + (size_t)row * DMODEL))[t] = orr;
}

// ---------------- TF32 tensor-core GEMM ----------------
// A is PRE-ROUNDED to tf32 by its producer (no cvt on A path).
#define LDA 20
#define LDB 72

template<int RELU, int ACCUM, int EXPERT, int GATHER, int QKV>
__global__ void __launch_bounds__(256)
tgemm(const float* __restrict__ A,
      const float* __restrict__ W0, const float* __restrict__ Wx1, const float* __restrict__ Wx2,
      const float* __restrict__ B0, const float* __restrict__ Bx1, const float* __restrict__ Bx2,
      float* __restrict__ C0, float* __restrict__ Cx1, float* __restrict__ Cx2,
      int M, int N, int K,
      const int* __restrict__ gather, const int* __restrict__ cnt,
      size_t aStride, size_t cStride)
{
    __shared__ __align__(16) unsigned As[2][128 * LDA];
    __shared__ __align__(16) unsigned Bs[2][16 * LDB];

    int e = EXPERT ? blockIdx.z : 0;
    int Mloc = EXPERT ? cnt[e] : M;
    int mBase = blockIdx.y * 128;
    if (mBase >= Mloc) return;
    int nBase = blockIdx.x * 64;

    const float* W = W0; const float* bias = B0; float* C = C0;
    if (QKV) {
        int z = blockIdx.z;
        if (z == 1)      { W = Wx1; bias = Bx1; C = Cx1; }
        else if (z == 2) { W = Wx2; bias = Bx2; C = Cx2; }
    }
    const float* Ap = A;
    if (EXPERT) {
        W = W0 + (size_t)e * K * N;
        bias = B0 + (size_t)e * N;
        C = C0 + (size_t)e * cStride;
        if (!GATHER) Ap = A + (size_t)e * aStride;
    }

    int tid = threadIdx.x;
    int lane = tid & 31, warp = tid >> 5;
    int wM = (warp & 1) * 64;
    int wN = (warp >> 1) * 16;
    int g = lane >> 2, t = lane & 3;

    int r0 = tid >> 2;
    int r1 = r0 + 64;
    int ac4 = (tid & 3) * 4;
    int m0 = mBase + r0; m0 = m0 < Mloc ? m0 : Mloc - 1;
    int m1 = mBase + r1; m1 = m1 < Mloc ? m1 : Mloc - 1;
    int ar0 = GATHER ? gather[e * MAXM + m0] : m0;
    int ar1 = GATHER ? gather[e * MAXM + m1] : m1;
    const float* pA0 = Ap + (size_t)ar0 * K + ac4;
    const float* pA1 = Ap + (size_t)ar1 * K + ac4;

    int br  = tid >> 4;
    int bc4 = (tid & 15) * 4;
    const float* pB = W + (size_t)br * N + nBase + bc4;

    float acc[4][2][4];
    #pragma unroll
    for (int i = 0; i < 4; i++)
        #pragma unroll
        for (int j = 0; j < 2; j++)
            #pragma unroll
            for (int q = 0; q < 4; q++) acc[i][j][q] = 0.0f;

    float4 sa0 = *(const float4*)pA0;
    float4 sa1 = *(const float4*)pA1;
    float4 sb  = *(const float4*)pB;

    int buf = 0;
    for (int k0 = 0; k0 < K; k0 += 16) {
        unsigned* As_ = As[buf];
        unsigned* Bs_ = Bs[buf];
        // A already tf32-rounded: bit-store as two STS.128
        *(uint4*)&As_[r0 * LDA + ac4] = *reinterpret_cast<uint4*>(&sa0);
        *(uint4*)&As_[r1 * LDA + ac4] = *reinterpret_cast<uint4*>(&sa1);
        // B: convert then one packed STS.128
        uint4 ub;
        ub.x = f2tf(sb.x); ub.y = f2tf(sb.y); ub.z = f2tf(sb.z); ub.w = f2tf(sb.w);
        *(uint4*)&Bs_[br * LDB + bc4] = ub;
        __syncthreads();

        if (k0 + 16 < K) {
            sa0 = *(const float4*)(pA0 + k0 + 16);
            sa1 = *(const float4*)(pA1 + k0 + 16);
            sb  = *(const float4*)(pB + (size_t)(k0 + 16) * N);
        }

        #pragma unroll
        for (int ks = 0; ks < 2; ks++) {
            unsigned af[4][4], bf[2][2];
            #pragma unroll
            for (int mt = 0; mt < 4; mt++) {
                int base = (wM + mt * 16 + g) * LDA + ks * 8 + t;
                af[mt][0] = As_[base];
                af[mt][1] = As_[base + 8 * LDA];
                af[mt][2] = As_[base + 4];
                af[mt][3] = As_[base + 8 * LDA + 4];
            }
            #pragma unroll
            for (int nt = 0; nt < 2; nt++) {
                int base = (ks * 8 + t) * LDB + wN + nt * 8 + g;
                bf[nt][0] = Bs_[base];
                bf[nt][1] = Bs_[base + 4 * LDB];
            }
            #pragma unroll
            for (int mt = 0; mt < 4; mt++)
                #pragma unroll
                for (int nt = 0; nt < 2; nt++)
                    asm volatile(
                        "mma.sync.aligned.m16n8k8.row.col.f32.tf32.tf32.f32 "
                        "{%0,%1,%2,%3}, {%4,%5,%6,%7}, {%8,%9}, {%0,%1,%2,%3};"
                        : "+f"(acc[mt][nt][0]), "+f"(acc[mt][nt][1]),
                          "+f"(acc[mt][nt][2]), "+f"(acc[mt][nt][3])
                        : "r"(af[mt][0]), "r"(af[mt][1]), "r"(af[mt][2]), "r"(af[mt][3]),
                          "r"(bf[nt][0]), "r"(bf[nt][1]));
        }
        buf ^= 1;
    }

    #pragma unroll
    for (int mt = 0; mt < 4; mt++) {
        #pragma unroll
        for (int half = 0; half < 2; half++) {
            int r = mBase + wM + mt * 16 + g + half * 8;
            if (r < Mloc) {
                #pragma unroll
                for (int nt = 0; nt < 2; nt++) {
                    int col = nBase + wN + nt * 8 + 2 * t;
                    float* cp = C + (size_t)r * N + col;
                    float v0 = acc[mt][nt][half * 2 + 0] + bias[col];
                    float v1 = acc[mt][nt][half * 2 + 1] + bias[col + 1];
                    if (RELU) {
                        // ReLU then pre-round for the downstream GEMM's A operand
                        v0 = roundtf(fmaxf(v0, 0.0f));
                        v1 = roundtf(fmaxf(v1, 0.0f));
                    }
                    if (ACCUM) { cp[0] += v0; cp[1] += v1; }
                    else       { cp[0] = v0;  cp[1] = v1; }
                }
            }
        }
    }
}

// ---------------- tiled attention ----------------
#define QT 32
#define KT 64
#define KVP 68                 // K/V smem row pitch (floats)
#define SCP 260                // score row pitch (floats, mult of 4)
#define ATTN_SMEM ((QT*KVP + KT*KVP + QT*SCP) * 4)

__global__ void __launch_bounds__(256)
attn2_kernel(const float* __restrict__ q, const float* __restrict__ k,
             const float* __restrict__ v, const int* __restrict__ abt,
             const float* __restrict__ bias_emb, float* __restrict__ o)
{
    extern __shared__ float sm[];
    float* Qs  = sm;                 // [QT][KVP]
    float* KVs = sm + QT * KVP;      // [KT][KVP]
    float* Sc  = KVs + KT * KVP;     // [QT][SCP]

    int bid = blockIdx.x;
    int qt = bid & 7, h = (bid >> 3) & 15, b = bid >> 7;
    int q0 = qt * QT;
    int t = threadIdx.x;
    int lane = t & 31, warp = t >> 5;

    // load Q tile (scaled by 1/8): row = t>>3, 8 floats at (t&7)*8
    {
        int r = t >> 3, c = (t & 7) * 8;
        const float* qg = q + (size_t)(b * SEQ + q0 + r) * DMODEL + h * HDIM + c;
        float4 a0 = *(const float4*)qg;
        float4 a1 = *(const float4*)(qg + 4);
        float* dst = Qs + r * KVP + c;
        dst[0] = a0.x * 0.125f; dst[1] = a0.y * 0.125f; dst[2] = a0.z * 0.125f; dst[3] = a0.w * 0.125f;
        dst[4] = a1.x * 0.125f; dst[5] = a1.y * 0.125f; dst[6] = a1.z * 0.125f; dst[7] = a1.w * 0.125f;
    }
    __syncthreads();

    int qq = t >> 3;      // owned query row (0..31)
    int kk = t & 7;

    // -------- pass 1: scores --------
    for (int kt = 0; kt < 4; kt++) {
        int k0 = kt * KT;
        {   // coalesced K tile load: row = t>>2, 16 floats at (t&3)*16
            int r = t >> 2, c = (t & 3) * 16;
            const float* kg = k + (size_t)(b * SEQ + k0 + r) * DMODEL + h * HDIM + c;
            float4 x0 = *(const float4*)kg;
            float4 x1 = *(const float4*)(kg + 4);
            float4 x2 = *(const float4*)(kg + 8);
            float4 x3 = *(const float4*)(kg + 12);
            float* dst = KVs + r * KVP + c;
            *(float4*)(dst)      = x0;
            *(float4*)(dst + 4)  = x1;
            *(float4*)(dst + 8)  = x2;
            *(float4*)(dst + 12) = x3;
        }
        __syncthreads();

        float acc[8] = {0, 0, 0, 0, 0, 0, 0, 0};
        #pragma unroll
        for (int d4 = 0; d4 < 16; d4++) {
            float4 qv = *(const float4*)(Qs + qq * KVP + d4 * 4);
            #pragma unroll
            for (int j = 0; j < 8; j++) {
                float4 kv = *(const float4*)(KVs + (kk + 8 * j) * KVP + d4 * 4);
                acc[j] += qv.x * kv.x + qv.y * kv.y + qv.z * kv.z + qv.w * kv.w;
            }
        }
        const int* arow = abt + (size_t)(b * SEQ + q0 + qq) * SEQ + k0;
        #pragma unroll
        for (int j = 0; j < 8; j++) {
            int bt = arow[kk + 8 * j];
            Sc[qq * SCP + k0 + kk + 8 * j] = acc[j] + bias_emb[bt * NH + h];
        }
        __syncthreads();
    }

    // -------- softmax (4 rows per warp, shuffle reductions) --------
    #pragma unroll
    for (int rr = 0; rr < 4; rr++) {
        int r = warp * 4 + rr;
        float vals[8];
        float mx = -3.4e38f;
        #pragma unroll
        for (int c = 0; c < 8; c++) {
            vals[c] = Sc[r * SCP + lane + 32 * c];
            mx = fmaxf(mx, vals[c]);
        }
        #pragma unroll
        for (int off = 16; off > 0; off >>= 1)
            mx = fmaxf(mx, __shfl_xor_sync(0xffffffffu, mx, off));
        float s = 0.0f;
        #pragma unroll
        for (int c = 0; c < 8; c++) { vals[c] = expf(vals[c] - mx); s += vals[c]; }
        #pragma unroll
        for (int off = 16; off > 0; off >>= 1)
            s += __shfl_xor_sync(0xffffffffu, s, off);
        float inv = 1.0f / s;
        #pragma unroll
        for (int c = 0; c < 8; c++)
            Sc[r * SCP + lane + 32 * c] = vals[c] * inv;
    }
    __syncthreads();

    // -------- pass 2: PV --------
    int dh = t & 7;
    float4 o0 = make_float4(0, 0, 0, 0);
    float4 o1 = make_float4(0, 0, 0, 0);
    for (int kt = 0; kt < 4; kt++) {
        int k0 = kt * KT;
        {   // coalesced V tile load
            int r = t >> 2, c = (t & 3) * 16;
            const float* vg = v + (size_t)(b * SEQ + k0 + r) * DMODEL + h * HDIM + c;
            float4 x0 = *(const float4*)vg;
            float4 x1 = *(const float4*)(vg + 4);
            float4 x2 = *(const float4*)(vg + 8);
            float4 x3 = *(const float4*)(vg + 12);
            float* dst = KVs + r * KVP + c;
            *(float4*)(dst)      = x0;
            *(float4*)(dst + 4)  = x1;
            *(float4*)(dst + 8)  = x2;
            *(float4*)(dst + 12) = x3;
        }
        __syncthreads();

        const float* prow = Sc + qq * SCP + k0;
        #pragma unroll
        for (int j4 = 0; j4 < 16; j4++) {
            float4 p4 = *(const float4*)(prow + j4 * 4);
            float pr[4] = {p4.x, p4.y, p4.z, p4.w};
            #pragma unroll
            for (int u = 0; u < 4; u++) {
                int j = j4 * 4 + u;
                float4 va = *(const float4*)(KVs + j * KVP + dh * 4);
                float4 vb = *(const float4*)(KVs + j * KVP + (dh + 8) * 4);
                float p = pr[u];
                o0.x += p * va.x; o0.y += p * va.y; o0.z += p * va.z; o0.w += p * va.w;
                o1.x += p * vb.x; o1.y += p * vb.y; o1.z += p * vb.z; o1.w += p * vb.w;
            }
        }
        __syncthreads();
    }

    // pre-round attention output (it is the A operand of the wo GEMM)
    o0.x = roundtf(o0.x); o0.y = roundtf(o0.y); o0.z = roundtf(o0.z); o0.w = roundtf(o0.w);
    o1.x = roundtf(o1.x); o1.y = roundtf(o1.y); o1.z = roundtf(o1.z); o1.w = roundtf(o1.w);
    float* og = o + (size_t)(b * SEQ + q0 + qq) * DMODEL + h * HDIM;
    *(float4*)(og + dh * 4) = o0;
    *(float4*)(og + 32 + dh * 4) = o1;
}

// ---------------- MoE routing ----------------
__global__ void reset_kernel() { if (threadIdx.x < NE) g_cnt[threadIdx.x] = 0; }

__global__ void route_kernel(const float* __restrict__ z, const float* __restrict__ gw,
                             const float* __restrict__ gb)
{
    __shared__ float lg[NE];
    int tok = blockIdx.x;
    int lane = threadIdx.x & 31, e = threadIdx.x >> 5;
    const float* zr = z + (size_t)tok * DMODEL;
    float s = 0.0f;
    for (int kk = lane; kk < DMODEL; kk += 32) s += zr[kk] * gw[kk * NE + e];
    #pragma unroll
    for (int off = 16; off > 0; off >>= 1) s += __shfl_down_sync(0xffffffffu, s, off);
    if (lane == 0) lg[e] = s + gb[e];
    __syncthreads();
    if (threadIdx.x == 0) {
        int i0 = 0; float v0 = lg[0];
        #pragma unroll
        for (int i = 1; i < NE; i++) if (lg[i] > v0) { v0 = lg[i]; i0 = i; }
        int i1 = -1; float v1 = -3.4e38f;
        #pragma unroll
        for (int i = 0; i < NE; i++) if (i != i0 && lg[i] > v1) { v1 = lg[i]; i1 = i; }
        float e1 = expf(v1 - v0);
        float invs = 1.0f / (1.0f + e1);
        float w0 = invs, w1 = e1 * invs;
        int p0 = atomicAdd(&g_cnt[i0], 1);
        g_ptok[i0 * MAXM + p0] = tok;
        g_pos[2 * tok] = i0 * MAXM + p0;
        g_wgt[2 * tok] = w0;
        int p1 = atomicAdd(&g_cnt[i1], 1);
        g_ptok[i1 * MAXM + p1] = tok;
        g_pos[2 * tok + 1] = i1 * MAXM + p1;
        g_wgt[2 * tok + 1] = w1;
    }
}

__global__ void combine_kernel()
{
    int tok = blockIdx.x, t = threadIdx.x;
    int p0 = g_pos[2 * tok], p1 = g_pos[2 * tok + 1];
    float w0 = g_wgt[2 * tok], w1 = g_wgt[2 * tok + 1];
    float4 a = ((const float4*)(g_y2 + (size_t)p0 * DMODEL))[t];
    float4 b = ((const float4*)(g_y2 + (size_t)p1 * DMODEL))[t];
    float4* f = (float4*)(g_feat + (size_t)tok * DMODEL);
    float4 fv = f[t];
    fv.x += w0 * a.x + w1 * b.x;
    fv.y += w0 * a.y + w1 * b.y;
    fv.z += w0 * a.z + w1 * b.z;
    fv.w += w0 * a.w + w1 * b.w;
    f[t] = fv;
}

// ---------------- host orchestration ----------------
extern "C" void kernel_launch(void* const* d_in, const int* in_sizes, int n_in,
                              void* d_out, int out_size)
{
    (void)in_sizes; (void)n_in; (void)out_size;
    const int*   et       = (const int*)d_in[0];
    const int*   xi       = (const int*)d_in[1];
    const int*   abt      = (const int*)d_in[2];
    const float* ent      = (const float*)d_in[3];
    const float* maskemb  = (const float*)d_in[4];
    const float* rel      = (const float*)d_in[5];
    const float* type     = (const float*)d_in[6];
    const float* bias_emb = (const float*)d_in[7];
    const float* ln1g     = (const float*)d_in[8];
    const float* ln1b     = (const float*)d_in[9];
    const float* wq       = (const float*)d_in[10];
    const float* bq       = (const float*)d_in[11];
    const float* wk       = (const float*)d_in[12];
    const float* bk       = (const float*)d_in[13];
    const float* wv       = (const float*)d_in[14];
    const float* bv       = (const float*)d_in[15];
    const float* wo       = (const float*)d_in[16];
    const float* bo       = (const float*)d_in[17];
    const float* ln2g     = (const float*)d_in[18];
    const float* ln2b     = (const float*)d_in[19];
    const float* gw       = (const float*)d_in[20];
    const float* gb       = (const float*)d_in[21];
    const float* w1       = (const float*)d_in[22];
    const float* b1       = (const float*)d_in[23];
    const float* w2       = (const float*)d_in[24];
    const float* b2       = (const float*)d_in[25];
    const float* flng     = (const float*)d_in[26];
    const float* flnb     = (const float*)d_in[27];
    float* out = (float*)d_out;

    float *feat, *xn, *xnr, *qb2, *kb2, *vb2, *ob, *hb, *yb;
    int *cntp, *ptokp;
    cudaGetSymbolAddress((void**)&feat,  g_feat);
    cudaGetSymbolAddress((void**)&xn,    g_xn);
    cudaGetSymbolAddress((void**)&xnr,   g_xnr);
    cudaGetSymbolAddress((void**)&qb2,   g_q);
    cudaGetSymbolAddress((void**)&kb2,   g_k);
    cudaGetSymbolAddress((void**)&vb2,   g_v);
    cudaGetSymbolAddress((void**)&ob,    g_o);
    cudaGetSymbolAddress((void**)&hb,    g_h);
    cudaGetSymbolAddress((void**)&yb,    g_y2);
    cudaGetSymbolAddress((void**)&cntp,  g_cnt);
    cudaGetSymbolAddress((void**)&ptokp, g_ptok);

    static int attn_attr_set = 0;
    if (!attn_attr_set) {
        cudaFuncSetAttribute(attn2_kernel,
                             cudaFuncAttributeMaxDynamicSharedMemorySize, ATTN_SMEM);
        attn_attr_set = 1;
    }

    embed_kernel<<<NTOK, 256>>>(et, xi, ent, maskemb, rel, type);

    for (int l = 0; l < 2; l++) {
        const size_t dd = (size_t)DMODEL * DMODEL;
        // 1) LN1 -> xn (exact, unused) + xnr (rounded, GEMM A)
        ln_kernel<<<NTOK, 256>>>(feat, ln1g + l * DMODEL, ln1b + l * DMODEL, xn, xnr);
        // 2) fused q,k,v projections (A = pre-rounded xnr)
        tgemm<0,0,0,0,1><<<dim3(16, 8, 3), 256>>>(
            xnr, wq + l * dd, wk + l * dd, wv + l * dd,
            bq + l * DMODEL, bk + l * DMODEL, bv + l * DMODEL,
            qb2, kb2, vb2,
            NTOK, DMODEL, DMODEL, (const int*)0, (const int*)0, 0, 0);
        // 3) attention (tiled); output pre-rounded for wo GEMM
        attn2_kernel<<<NB * NH * (SEQ / QT), 256, ATTN_SMEM>>>(
            qb2, kb2, vb2, abt, bias_emb, ob);
        // 4) out proj + residual accumulate
        tgemm<0,1,0,0,0><<<dim3(16, 8), 256>>>(
            ob, wo + l * dd, (const float*)0, (const float*)0,
            bo + l * DMODEL, (const float*)0, (const float*)0,
            feat, (float*)0, (float*)0,
            NTOK, DMODEL, DMODEL, (const int*)0, (const int*)0, 0, 0);
        // 5) LN2 -> xn (exact, for routing) + xnr (rounded, GEMM A)
        ln_kernel<<<NTOK, 256>>>(feat, ln2g + l * DMODEL, ln2b + l * DMODEL, xn, xnr);
        // 6) routing on exact xn
        reset_kernel<<<1, 32>>>();
        route_kernel<<<NTOK, 256>>>(xn, gw + (size_t)l * DMODEL * NE, gb + l * NE);
        // 7) expert up-proj + relu (gathered rows of xnr); output pre-rounded
        tgemm<1,0,1,1,0><<<dim3(32, 8, 8), 256>>>(
            xnr, w1 + (size_t)l * NE * DMODEL * DHID, (const float*)0, (const float*)0,
            b1 + (size_t)l * NE * DHID, (const float*)0, (const float*)0,
            hb, (float*)0, (float*)0,
            MAXM, DHID, DMODEL, ptokp, cntp, 0, (size_t)MAXM * DHID);
        // 8) expert down-proj (A = pre-rounded hb)
        tgemm<0,0,1,0,0><<<dim3(16, 8, 8), 256>>>(
            hb, w2 + (size_t)l * NE * DHID * DMODEL, (const float*)0, (const float*)0,
            b2 + (size_t)l * NE * DMODEL, (const float*)0, (const float*)0,
            yb, (float*)0, (float*)0,
            MAXM, DMODEL, DHID, (const int*)0, cntp, (size_t)MAXM * DHID, (size_t)MAXM * DMODEL);
        // 9) weighted combine into feat
        combine_kernel<<<NTOK, 256>>>();
    }

    // final layernorm -> out (exact); rounded copy goes to scratch
    ln_kernel<<<NTOK, 256>>>(feat, flng, flnb, out, xnr);
}